// round 17
// baseline (speedup 1.0000x reference)
#include <cuda_runtime.h>
#include <cuda_fp16.h>
#include <cstdint>

#define BS      2
#define TT      8
#define NOBJ    4
#define CH      64
#define CH2     32
#define DIM     64
#define NN      1024
#define BTO     64
#define KBN     16

#define QSCALE  1.4426950408889634f   // log2(e)

__device__ __half g_Kt[KBN * NN * CH2];   // [kb][m][o] fp16 (transposed)
__device__ __half g_V[KBN * DIM * NN];    // [kb][d][n] fp16

__device__ __forceinline__ uint32_t smem_u32(const void* p) {
    uint32_t a;
    asm("{ .reg .u64 t; cvta.to.shared.u64 t, %1; cvt.u32.u64 %0, t; }" : "=r"(a) : "l"(p));
    return a;
}
__device__ __forceinline__ void ldsm_x4(uint32_t* r, uint32_t addr) {
    asm volatile("ldmatrix.sync.aligned.m8n8.x4.shared.b16 {%0,%1,%2,%3}, [%4];"
                 : "=r"(r[0]), "=r"(r[1]), "=r"(r[2]), "=r"(r[3]) : "r"(addr));
}
__device__ __forceinline__ void mma16816(float* d, const uint32_t* a, const uint32_t* b) {
    asm volatile("mma.sync.aligned.m16n8k16.row.col.f32.f16.f16.f32 "
                 "{%0,%1,%2,%3}, {%4,%5,%6,%7}, {%8,%9}, {%0,%1,%2,%3};"
                 : "+f"(d[0]), "+f"(d[1]), "+f"(d[2]), "+f"(d[3])
                 : "r"(a[0]), "r"(a[1]), "r"(a[2]), "r"(a[3]), "r"(b[0]), "r"(b[1]));
}
__device__ __forceinline__ void cp_async16(uint32_t dst, const void* src) {
    asm volatile("cp.async.cg.shared.global [%0], [%1], 16;" :: "r"(dst), "l"(src));
}
__device__ __forceinline__ float ex2f(float x) {
    float r; asm("ex2.approx.ftz.f32 %0, %1;" : "=f"(r) : "f"(x)); return r;
}
#define CP_COMMIT() asm volatile("cp.async.commit_group;" ::: "memory")
#define CP_WAIT(n)  asm volatile("cp.async.wait_group %0;" :: "n"(n) : "memory")

// ---------------------------------------------------------------------------
// Kernel 1: K/V projections only (Q moved into fused). 192 blocks,
// 16 out channels, 2 n per thread.
//   [0,64):   K  kb=id>>2, sub=(id>>1)&1, nt=id&1
//   [64,192): V  kb=id>>3, sub=(id>>1)&3, nt=id&1
// ---------------------------------------------------------------------------
__global__ void __launch_bounds__(256) qkv_kernel(
    const float* __restrict__ inp,
    const float* __restrict__ wk, const float* __restrict__ bk,
    const float* __restrict__ wv, const float* __restrict__ bv)
{
    __shared__ float sw[16 * CH];
    __shared__ float sb[16];
    __shared__ __half sk[512 * 16];

    const int tid = threadIdx.x;
    const int bid = blockIdx.x;

    const float *X, *W, *B;
    size_t obase = 0;
    int nt, role, sub;

    if (bid < 64) {
        const int id = bid;
        const int kb = id >> 2; sub = (id >> 1) & 1; nt = id & 1; role = 1;
        X = inp + (size_t)kb * CH * NN;
        W = wk + sub * 16 * CH; B = bk + sub * 16;
        obase = (size_t)kb * NN * CH2;
    } else {
        const int id = bid - 64;
        const int kb = id >> 3; sub = (id >> 1) & 3; nt = id & 1; role = 2;
        X = inp + (size_t)kb * CH * NN;
        W = wv + sub * 16 * CH; B = bv + sub * 16;
        obase = (size_t)kb * DIM * NN + (size_t)sub * 16 * NN;
    }

    for (int i = tid; i < 16 * CH; i += 256) sw[i] = W[i];
    if (tid < 16) sb[tid] = B[tid];
    __syncthreads();

    const int n0 = nt * 512 + tid;
    const int n1 = n0 + 256;
    float acc0[16], acc1[16];
    #pragma unroll
    for (int o = 0; o < 16; o++) { acc0[o] = 0.f; acc1[o] = 0.f; }

    #pragma unroll
    for (int c0 = 0; c0 < CH; c0 += 8) {
        float x0[8], x1[8];
        #pragma unroll
        for (int j = 0; j < 8; j++) {
            x0[j] = X[(c0 + j) * NN + n0];
            x1[j] = X[(c0 + j) * NN + n1];
        }
        #pragma unroll
        for (int o = 0; o < 16; o++) {
            const float4 wa = *(const float4*)&sw[o * CH + c0];
            const float4 wb = *(const float4*)&sw[o * CH + c0 + 4];
            acc0[o] = fmaf(wa.x, x0[0], acc0[o]); acc1[o] = fmaf(wa.x, x1[0], acc1[o]);
            acc0[o] = fmaf(wa.y, x0[1], acc0[o]); acc1[o] = fmaf(wa.y, x1[1], acc1[o]);
            acc0[o] = fmaf(wa.z, x0[2], acc0[o]); acc1[o] = fmaf(wa.z, x1[2], acc1[o]);
            acc0[o] = fmaf(wa.w, x0[3], acc0[o]); acc1[o] = fmaf(wa.w, x1[3], acc1[o]);
            acc0[o] = fmaf(wb.x, x0[4], acc0[o]); acc1[o] = fmaf(wb.x, x1[4], acc1[o]);
            acc0[o] = fmaf(wb.y, x0[5], acc0[o]); acc1[o] = fmaf(wb.y, x1[5], acc1[o]);
            acc0[o] = fmaf(wb.z, x0[6], acc0[o]); acc1[o] = fmaf(wb.z, x1[6], acc1[o]);
            acc0[o] = fmaf(wb.w, x0[7], acc0[o]); acc1[o] = fmaf(wb.w, x1[7], acc1[o]);
        }
    }

    if (role == 2) {
        #pragma unroll
        for (int o = 0; o < 16; o++) {
            g_V[obase + o * NN + n0] = __float2half(acc0[o] + sb[o]);
            g_V[obase + o * NN + n1] = __float2half(acc1[o] + sb[o]);
        }
    } else {
        #pragma unroll
        for (int o = 0; o < 16; o++) {
            sk[tid * 16 + o]         = __float2half(acc0[o] + sb[o]);
            sk[(tid + 256) * 16 + o] = __float2half(acc1[o] + sb[o]);
        }
        __syncthreads();
        {
            const __half* s0 = &sk[tid * 16];
            const __half* s1 = &sk[(tid + 256) * 16];
            __half* d0 = g_Kt + obase + (size_t)(nt * 512 + tid) * CH2 + sub * 16;
            __half* d1 = g_Kt + obase + (size_t)(nt * 512 + tid + 256) * CH2 + sub * 16;
            *(uint4*)d0       = *(const uint4*)s0;
            *(uint4*)(d0 + 8) = *(const uint4*)(s0 + 8);
            *(uint4*)d1       = *(const uint4*)s1;
            *(uint4*)(d1 + 8) = *(const uint4*)(s1 + 8);
        }
    }
}

// ---------------------------------------------------------------------------
// Persistent fused kernel. K (64KB, XOR-swizzled) + V (128KB, XOR-swizzled)
// resident; Q projection computed in-block during the fill; 4 iters of m16.
// grid=(16, 64), block=256. Op reduce in 2 chunks (6 barriers/iter).
// Swizzle: f(row,u16B) = (u & ~7) | ((u & low) ^ s(row)); K: s=(row>>1)&3 on
// 4 units; V: s=row&7 on 128 units. Fill and ldsm use the same f.
// ---------------------------------------------------------------------------
#define QSS 40
#define OPS 34

#define FS_KS 0            // 65536
#define FS_VS 65536        // 131072 -> 196608
#define FS_QH 196608       // 64*40*2 = 5120 -> 201728
#define FS_RS 201728       // 512 -> 202240
#define FS_OP 202240       // 8*16*34*4 = 17408 -> 219648
#define FS_W  219648       // 8192 + 128 -> 227968
#define FUSED_SMEM 227968

extern __shared__ __align__(16) unsigned char fsm[];

__global__ void __launch_bounds__(256, 1) fused_kernel(
    float* __restrict__ attn_out, float* __restrict__ out,
    const float* __restrict__ dyn,
    const float* __restrict__ wq, const float* __restrict__ bq)
{
    __half* Qh  = (__half*)(fsm + FS_QH);
    float* redS = (float*)(fsm + FS_RS);
    float* Op   = (float*)(fsm + FS_OP);
    float* swT  = (float*)(fsm + FS_W);          // [c][o] transposed Wq
    float* sbq  = (float*)(fsm + FS_W + 8192);

    const int tid  = threadIdx.x;
    const int nq   = tid >> 5, lane = tid & 31;
    const int b    = blockIdx.y;
    const int mg   = blockIdx.x;
    const int kb   = (b >> 5) * TT + (b & 7);
    const int g    = lane >> 2, tig = lane & 3;

    const uint32_t uK = smem_u32(fsm + FS_KS);
    const uint32_t uV = smem_u32(fsm + FS_VS);

    const __half* Kg = g_Kt + (size_t)kb * NN * CH2;
    const __half* Vg = g_V + (size_t)kb * DIM * NN;

    // ---- issue K fill (group 0), swizzled: unit oq -> oq ^ ((key>>1)&3) ----
    #pragma unroll
    for (int i = 0; i < 16; i++) {
        const int idx = i * 256 + tid;
        const int key = idx >> 2, oq = idx & 3;
        const int swz = oq ^ ((key >> 1) & 3);
        cp_async16(uK + (uint32_t)(key * 64 + swz * 16),
                   Kg + (size_t)key * CH2 + oq * 8);
    }
    CP_COMMIT();
    // ---- issue V fill (group 1), swizzled: unit kq -> kq ^ (d&7) ----
    #pragma unroll
    for (int i = 0; i < 32; i++) {
        const int idx = i * 256 + tid;
        const int d = idx >> 7, kq = idx & 127;
        const int swz = kq ^ (d & 7);
        cp_async16(uV + (uint32_t)(d * 2048 + swz * 16),
                   Vg + (size_t)d * NN + kq * 8);
    }
    CP_COMMIT();

    // ---- load Wq transposed + bias (under fill) ----
    #pragma unroll
    for (int i = 0; i < 8; i++) {
        const int lin = i * 256 + tid;            // 2048
        const int o = lin >> 6, c = lin & 63;
        swT[c * 32 + o] = wq[lin];
    }
    if (tid < 32) sbq[tid] = bq[tid];
    __syncthreads();

    // ---- Q projection for this block's 64 m-rows (hidden under fill) ----
    {
        const int j = tid & 63, og = tid >> 6;
        float qa[8];
        #pragma unroll
        for (int o = 0; o < 8; o++) qa[o] = 0.f;
        const float* Xd = dyn + (size_t)b * CH * NN + mg * 64 + j;
        #pragma unroll 8
        for (int c = 0; c < CH; c++) {
            const float x = Xd[(size_t)c * NN];
            const float4 w0 = *(const float4*)&swT[c * 32 + og * 8];
            const float4 w1 = *(const float4*)&swT[c * 32 + og * 8 + 4];
            qa[0] = fmaf(w0.x, x, qa[0]); qa[1] = fmaf(w0.y, x, qa[1]);
            qa[2] = fmaf(w0.z, x, qa[2]); qa[3] = fmaf(w0.w, x, qa[3]);
            qa[4] = fmaf(w1.x, x, qa[4]); qa[5] = fmaf(w1.y, x, qa[5]);
            qa[6] = fmaf(w1.z, x, qa[6]); qa[7] = fmaf(w1.w, x, qa[7]);
        }
        __half hq[8];
        #pragma unroll
        for (int o = 0; o < 8; o++)
            hq[o] = __float2half((qa[o] + sbq[og * 8 + o]) * QSCALE);
        *(uint4*)&Qh[j * QSS + og * 8] = *(const uint4*)hq;
    }
    CP_WAIT(1);                // K resident
    __syncthreads();

    // lane constants
    const uint32_t brow = (lane & 7) + ((lane >> 4) & 1) * 8;
    const int u0   = (lane >> 3) & 1;
    const int sk_  = (lane >> 1) & 3;                    // K swizzle (row bits 1-2)
    const uint32_t cu0 = (uint32_t)((u0 ^ sk_) * 16);
    const uint32_t cu1 = (uint32_t)(((u0 + 2) ^ sk_) * 16);
    const int ubase = nq * 2 + u0;
    const uint32_t vconst = (uint32_t)((((ubase & 7) ^ (lane & 7)) | (ubase & 8)) * 16);
    const uint32_t vrow = uV + brow * 2048 + vconst;     // + dt*32768 + c*256
    const uint32_t kBase = uK + brow * 64;

    const int rowA = g, rowB = g + 8;

    #pragma unroll 1
    for (int it = 0; it < 4; it++) {
        const int m0 = mg * 64 + it * 16;

        // ---- phase 1: energy MMA (warp: 16m x 256n x 32k), pure fp16 ----
        const uint32_t aoff = smem_u32(Qh) +
            (uint32_t)(((it * 16 + (lane & 15)) * QSS + (lane >> 4) * 8) * 2);
        uint32_t ah0[4], ah1[4];
        ldsm_x4(ah0, aoff);
        ldsm_x4(ah1, aoff + 32);

        float acc[8][8];
        #pragma unroll
        for (int l = 0; l < 8; l++)
            #pragma unroll
            for (int c = 0; c < 8; c++) acc[l][c] = 0.f;

        #pragma unroll
        for (int CC = 0; CC < 4; CC++) {
            #pragma unroll
            for (int ti = 0; ti < 2; ti++) {
                const int t = nq + ti * 8;
                const uint32_t ra = kBase + (uint32_t)((CC * 256 + t * 16) * 64);
                uint32_t b0[4], b1[4];
                ldsm_x4(b0, ra + cu0);
                ldsm_x4(b1, ra + cu1);
                float* A = acc[CC * 2 + ti];
                mma16816(A + 0, ah0, b0 + 0); mma16816(A + 4, ah0, b0 + 2);
                mma16816(A + 0, ah1, b1 + 0); mma16816(A + 4, ah1, b1 + 2);
            }
        }

        // ---- phase 2: exp2 + row-sum across 8 warps ----
        float sA = 0.f, sB = 0.f;
        #pragma unroll
        for (int l = 0; l < 8; l++) {
            acc[l][0] = ex2f(acc[l][0]); acc[l][1] = ex2f(acc[l][1]);
            acc[l][4] = ex2f(acc[l][4]); acc[l][5] = ex2f(acc[l][5]);
            acc[l][2] = ex2f(acc[l][2]); acc[l][3] = ex2f(acc[l][3]);
            acc[l][6] = ex2f(acc[l][6]); acc[l][7] = ex2f(acc[l][7]);
            sA += acc[l][0] + acc[l][1] + acc[l][4] + acc[l][5];
            sB += acc[l][2] + acc[l][3] + acc[l][6] + acc[l][7];
        }
        sA += __shfl_xor_sync(0xffffffffu, sA, 1);
        sA += __shfl_xor_sync(0xffffffffu, sA, 2);
        sB += __shfl_xor_sync(0xffffffffu, sB, 1);
        sB += __shfl_xor_sync(0xffffffffu, sB, 2);
        if (tig == 0) { redS[nq * 16 + rowA] = sA; redS[nq * 16 + rowB] = sB; }
        __syncthreads();
        sA = 0.f; sB = 0.f;
        #pragma unroll
        for (int s = 0; s < 8; s++) {
            sA += redS[s * 16 + rowA];
            sB += redS[s * 16 + rowB];
        }
        const float invA = 1.f / sA, invB = 1.f / sB;

        // ---- V resident before first AV ----
        if (it == 0) { CP_WAIT(0); __syncthreads(); }

        // ---- phase 3: merged pf-build + AV MMA + attn STG per c ----
        float acc2[32];
        #pragma unroll
        for (int i = 0; i < 32; i++) acc2[i] = 0.f;

        float* arow0 = attn_out + ((size_t)b * NN + m0 + rowA) * NN;
        float* arow1 = attn_out + ((size_t)b * NN + m0 + rowB) * NN;

        #pragma unroll
        for (int c = 0; c < 8; c++) {
            const float p00 = acc[c][0] * invA, p01 = acc[c][1] * invA;
            const float p10 = acc[c][4] * invA, p11 = acc[c][5] * invA;
            const float p20 = acc[c][2] * invB, p21 = acc[c][3] * invB;
            const float p30 = acc[c][6] * invB, p31 = acc[c][7] * invB;
            uint32_t pf[4];
            {
                const __half2 f0 = __floats2half2_rn(p00, p01);
                const __half2 f1 = __floats2half2_rn(p20, p21);
                const __half2 f2 = __floats2half2_rn(p10, p11);
                const __half2 f3 = __floats2half2_rn(p30, p31);
                pf[0] = *(const uint32_t*)&f0;
                pf[1] = *(const uint32_t*)&f1;
                pf[2] = *(const uint32_t*)&f2;
                pf[3] = *(const uint32_t*)&f3;
            }
            #pragma unroll
            for (int dt = 0; dt < 4; dt++) {
                uint32_t bf[4];
                ldsm_x4(bf, vrow + (uint32_t)(dt * 32768 + c * 256));
                mma16816(acc2 + dt * 8,     pf, bf);
                mma16816(acc2 + dt * 8 + 4, pf, bf + 2);
            }
            const int c0 = c * 128 + nq * 16 + tig * 2;
            *(float2*)&arow0[c0]     = make_float2(p00, p01);
            *(float2*)&arow0[c0 + 8] = make_float2(p10, p11);
            *(float2*)&arow1[c0]     = make_float2(p20, p21);
            *(float2*)&arow1[c0 + 8] = make_float2(p30, p31);
        }

        // ---- Op reduce in 2 d-chunks of 32 ----
        #pragma unroll
        for (int dc = 0; dc < 2; dc++) {
            __syncthreads();
            {
                float* Ops = Op + nq * (16 * OPS);
                #pragma unroll
                for (int dtl = 0; dtl < 2; dtl++) {
                    const int dt = dc * 2 + dtl;
                    #pragma unroll
                    for (int sub = 0; sub < 2; sub++) {
                        const int dl = dtl * 16 + sub * 8 + tig * 2;
                        *(float2*)&Ops[rowA * OPS + dl] =
                            make_float2(acc2[dt * 8 + sub * 4 + 0], acc2[dt * 8 + sub * 4 + 1]);
                        *(float2*)&Ops[rowB * OPS + dl] =
                            make_float2(acc2[dt * 8 + sub * 4 + 2], acc2[dt * 8 + sub * 4 + 3]);
                    }
                }
            }
            __syncthreads();
            {
                const int dl = tid >> 3, m2 = (tid & 7) * 2;
                float s0 = 0.f, s1 = 0.f;
                #pragma unroll
                for (int sl = 0; sl < 8; sl++) {
                    const int base = sl * (16 * OPS) + dl;
                    s0 += Op[base + m2 * OPS];
                    s1 += Op[base + (m2 + 1) * OPS];
                }
                *(float2*)&out[(size_t)b * DIM * NN + (size_t)(dc * 32 + dl) * NN + m0 + m2] =
                    make_float2(s0, s1);
            }
        }
    }
}

// ---------------------------------------------------------------------------
extern "C" void kernel_launch(void* const* d_in, const int* in_sizes, int n_in,
                              void* d_out, int out_size)
{
    const float* inp = (const float*)d_in[0];
    const float* dyn = (const float*)d_in[1];
    const float* wq  = (const float*)d_in[2];
    const float* bq  = (const float*)d_in[3];
    const float* wk  = (const float*)d_in[4];
    const float* bk  = (const float*)d_in[5];
    const float* wv  = (const float*)d_in[6];
    const float* bv  = (const float*)d_in[7];

    float* out  = (float*)d_out;
    float* attn = out + (size_t)BTO * DIM * NN;

    static bool attr_done = false;
    if (!attr_done) {
        cudaFuncSetAttribute(fused_kernel, cudaFuncAttributeMaxDynamicSharedMemorySize, FUSED_SMEM);
        attr_done = true;
    }

    qkv_kernel<<<192, 256>>>(inp, wk, bk, wv, bv);
    fused_kernel<<<dim3(16, BTO), 256, FUSED_SMEM>>>(attn, out, dyn, wq, bq);
}